// round 1
// baseline (speedup 1.0000x reference)
#include <cuda_runtime.h>
#include <math.h>

#define BATCH 8
#define SEQ 1024
#define NDIM 768
#define HEADS 12
#define DHEAD 64
#define INNER 768
#define QKV_COLS 2304

// Scratch: static device globals (no cudaMalloc allowed).
__device__ float g_qkv[BATCH * SEQ * QKV_COLS];   // [b, n, 2304]
__device__ float g_att[BATCH * SEQ * NDIM];       // [b, n, 768]

// ---------------------------------------------------------------------------
// SGEMM (NT): C[M,N] = A[M,K] @ B[N,K]^T (+ bias[N])
// 128x128 tile, BK=8, 256 threads, 8x8 per thread.
// ---------------------------------------------------------------------------
template <bool HAS_BIAS>
__global__ void __launch_bounds__(256) sgemm_nt(const float* __restrict__ A,
                                                const float* __restrict__ B,
                                                const float* __restrict__ bias,
                                                float* __restrict__ C,
                                                int M, int N, int K) {
    const int BM = 128, BN = 128, BK = 8;
    __shared__ float As[BK][BM];
    __shared__ float Bs[BK][BN];

    const int tid = threadIdx.x;
    const int bm = blockIdx.y * BM;
    const int bn = blockIdx.x * BN;
    const int tx = tid & 15;   // 0..15 -> 8 cols each
    const int ty = tid >> 4;   // 0..15 -> 8 rows each

    const int lr = tid >> 1;          // 0..127
    const int lc = (tid & 1) * 4;     // 0 or 4

    const float* Aptr = A + (size_t)(bm + lr) * K + lc;
    const float* Bptr = B + (size_t)(bn + lr) * K + lc;

    float acc[8][8];
#pragma unroll
    for (int i = 0; i < 8; i++)
#pragma unroll
        for (int j = 0; j < 8; j++) acc[i][j] = 0.0f;

    for (int k0 = 0; k0 < K; k0 += BK) {
        float4 a4 = *(const float4*)(Aptr + k0);
        float4 b4 = *(const float4*)(Bptr + k0);
        As[lc + 0][lr] = a4.x; As[lc + 1][lr] = a4.y;
        As[lc + 2][lr] = a4.z; As[lc + 3][lr] = a4.w;
        Bs[lc + 0][lr] = b4.x; Bs[lc + 1][lr] = b4.y;
        Bs[lc + 2][lr] = b4.z; Bs[lc + 3][lr] = b4.w;
        __syncthreads();

#pragma unroll
        for (int kk = 0; kk < BK; kk++) {
            float4 a0 = *(const float4*)&As[kk][ty * 8];
            float4 a1 = *(const float4*)&As[kk][ty * 8 + 4];
            float4 b0 = *(const float4*)&Bs[kk][tx * 8];
            float4 b1 = *(const float4*)&Bs[kk][tx * 8 + 4];
            float ar[8] = {a0.x, a0.y, a0.z, a0.w, a1.x, a1.y, a1.z, a1.w};
            float br[8] = {b0.x, b0.y, b0.z, b0.w, b1.x, b1.y, b1.z, b1.w};
#pragma unroll
            for (int i = 0; i < 8; i++)
#pragma unroll
                for (int j = 0; j < 8; j++)
                    acc[i][j] = fmaf(ar[i], br[j], acc[i][j]);
        }
        __syncthreads();
    }

#pragma unroll
    for (int i = 0; i < 8; i++) {
        const int row = bm + ty * 8 + i;
        float* cp = C + (size_t)row * N + bn + tx * 8;
        float bsum0[4], bsum1[4];
#pragma unroll
        for (int j = 0; j < 4; j++) {
            float bb0 = HAS_BIAS ? bias[bn + tx * 8 + j] : 0.0f;
            float bb1 = HAS_BIAS ? bias[bn + tx * 8 + 4 + j] : 0.0f;
            bsum0[j] = acc[i][j] + bb0;
            bsum1[j] = acc[i][4 + j] + bb1;
        }
        *(float4*)(cp)     = make_float4(bsum0[0], bsum0[1], bsum0[2], bsum0[3]);
        *(float4*)(cp + 4) = make_float4(bsum1[0], bsum1[1], bsum1[2], bsum1[3]);
    }
}

// ---------------------------------------------------------------------------
// Fused shuffled-Q flash attention.
// Block: 128 threads. Tile: 64 q-rows x full head (d=64), kv tiles of 64.
// Thread map: tx = tid&7 (8 col-groups of 8), ty = tid>>3 (16 row-groups of 4).
// smem: Qs[64][66], Kt[64][68] (d-major), Vs[64][68], Ss[64][66]
// ---------------------------------------------------------------------------
#define QW 66
#define KW 68
#define VW 68
#define SW 66
#define ATT_SMEM ((64 * QW + 64 * KW + 64 * VW + 64 * SW) * 4)

__global__ void __launch_bounds__(128) attn_kernel(const float* __restrict__ qkv,
                                                   const int* __restrict__ perms,
                                                   float* __restrict__ att_out) {
    extern __shared__ float sm[];
    float* Qs = sm;                 // [64][QW]
    float* Kt = Qs + 64 * QW;       // [64][KW]  (index: [d][m])
    float* Vs = Kt + 64 * KW;       // [64][VW]  (index: [m][d])
    float* Ss = Vs + 64 * VW;       // [64][SW]

    const int bh = blockIdx.y;
    const int b = bh / HEADS;
    const int h = bh % HEADS;
    const int q0 = blockIdx.x * 64;

    const int tid = threadIdx.x;
    const int tx = tid & 7;    // 0..7  -> 8 cols each
    const int ty = tid >> 3;   // 0..15 -> 4 rows each
    const float scale = 0.125f;  // 64^-0.5

    const float* qkv_b = qkv + (size_t)b * SEQ * QKV_COLS;
    const int hoff = h * DHEAD;

    // Gather permuted Q tile (scale folded in).
    const int* ph = perms + (size_t)h * (SEQ * DHEAD) + q0 * DHEAD;
#pragma unroll 4
    for (int it = 0; it < 32; it++) {
        int f = it * 128 + tid;           // f = i*64 + j
        int p = ph[f];
        int nn = p >> 6;
        int dd = p & 63;
        int i = f >> 6, j = f & 63;
        Qs[i * QW + j] = qkv_b[(size_t)nn * QKV_COLS + hoff + dd] * scale;
    }

    float m_i[4] = {-1e30f, -1e30f, -1e30f, -1e30f};
    float l_i[4] = {0.f, 0.f, 0.f, 0.f};
    float o[4][8];
#pragma unroll
    for (int i = 0; i < 4; i++)
#pragma unroll
        for (int j = 0; j < 8; j++) o[i][j] = 0.f;

    for (int t = 0; t < 16; t++) {
        __syncthreads();  // previous O-accum done (and Qs ready on t=0)
        const int m0 = t * 64;
        // Load K (transposed -> Kt[d][m]) and V (natural -> Vs[m][d]).
#pragma unroll
        for (int it = 0; it < 8; it++) {
            int fi = it * 128 + tid;          // float4 index, 0..1023
            int m = fi >> 4;
            int dg = (fi & 15) * 4;
            const float* base = qkv_b + (size_t)(m0 + m) * QKV_COLS + hoff + dg;
            float4 kk = *(const float4*)(base + INNER);
            Kt[(dg + 0) * KW + m] = kk.x;
            Kt[(dg + 1) * KW + m] = kk.y;
            Kt[(dg + 2) * KW + m] = kk.z;
            Kt[(dg + 3) * KW + m] = kk.w;
            float4 vv = *(const float4*)(base + 2 * INNER);
            *(float4*)&Vs[m * VW + dg] = vv;
        }
        __syncthreads();

        // S = (Q*scale) @ K^T   (4x8 per thread)
        float s[4][8];
#pragma unroll
        for (int i = 0; i < 4; i++)
#pragma unroll
            for (int j = 0; j < 8; j++) s[i][j] = 0.f;

#pragma unroll 4
        for (int d = 0; d < 64; d++) {
            float4 k0 = *(const float4*)&Kt[d * KW + tx * 8];
            float4 k1 = *(const float4*)&Kt[d * KW + tx * 8 + 4];
            float kr[8] = {k0.x, k0.y, k0.z, k0.w, k1.x, k1.y, k1.z, k1.w};
            float qa[4];
#pragma unroll
            for (int i = 0; i < 4; i++) qa[i] = Qs[(ty * 4 + i) * QW + d];
#pragma unroll
            for (int i = 0; i < 4; i++)
#pragma unroll
                for (int j = 0; j < 8; j++)
                    s[i][j] = fmaf(qa[i], kr[j], s[i][j]);
        }

        // Online softmax update per row.
#pragma unroll
        for (int i = 0; i < 4; i++) {
            float rm = s[i][0];
#pragma unroll
            for (int j = 1; j < 8; j++) rm = fmaxf(rm, s[i][j]);
#pragma unroll
            for (int off = 4; off > 0; off >>= 1)
                rm = fmaxf(rm, __shfl_xor_sync(0xffffffffu, rm, off));
            float mnew = fmaxf(m_i[i], rm);
            float rsum = 0.f;
#pragma unroll
            for (int j = 0; j < 8; j++) {
                s[i][j] = __expf(s[i][j] - mnew);
                rsum += s[i][j];
            }
#pragma unroll
            for (int off = 4; off > 0; off >>= 1)
                rsum += __shfl_xor_sync(0xffffffffu, rsum, off);
            float alpha = __expf(m_i[i] - mnew);
            l_i[i] = l_i[i] * alpha + rsum;
#pragma unroll
            for (int j = 0; j < 8; j++) o[i][j] *= alpha;
            m_i[i] = mnew;
            // stage P
            float* sp = &Ss[(ty * 4 + i) * SW + tx * 8];
#pragma unroll
            for (int j = 0; j < 8; j++) sp[j] = s[i][j];
        }
        __syncthreads();

        // O += P @ V   (4x8 per thread)
#pragma unroll 4
        for (int c = 0; c < 64; c++) {
            float4 v0 = *(const float4*)&Vs[c * VW + tx * 8];
            float4 v1 = *(const float4*)&Vs[c * VW + tx * 8 + 4];
            float vr[8] = {v0.x, v0.y, v0.z, v0.w, v1.x, v1.y, v1.z, v1.w};
            float pa[4];
#pragma unroll
            for (int i = 0; i < 4; i++) pa[i] = Ss[(ty * 4 + i) * SW + c];
#pragma unroll
            for (int i = 0; i < 4; i++)
#pragma unroll
                for (int j = 0; j < 8; j++)
                    o[i][j] = fmaf(pa[i], vr[j], o[i][j]);
        }
    }

    // Epilogue: normalize and write [b, q0+row, h*64 + col]
#pragma unroll
    for (int i = 0; i < 4; i++) {
        float inv = 1.0f / l_i[i];
        int row = q0 + ty * 4 + i;
        float* op = att_out + ((size_t)b * SEQ + row) * NDIM + hoff + tx * 8;
        *(float4*)(op) = make_float4(o[i][0] * inv, o[i][1] * inv,
                                     o[i][2] * inv, o[i][3] * inv);
        *(float4*)(op + 4) = make_float4(o[i][4] * inv, o[i][5] * inv,
                                         o[i][6] * inv, o[i][7] * inv);
    }
}

// ---------------------------------------------------------------------------
extern "C" void kernel_launch(void* const* d_in, const int* in_sizes, int n_in,
                              void* d_out, int out_size) {
    const float* x     = (const float*)d_in[0];
    const float* w_qkv = (const float*)d_in[1];
    const float* w_out = (const float*)d_in[2];
    const float* b_out = (const float*)d_in[3];
    const int*   perms = (const int*)d_in[4];
    float* out = (float*)d_out;

    float* qkv = nullptr;
    float* att = nullptr;
    cudaGetSymbolAddress((void**)&qkv, g_qkv);
    cudaGetSymbolAddress((void**)&att, g_att);

    cudaFuncSetAttribute(attn_kernel, cudaFuncAttributeMaxDynamicSharedMemorySize,
                         ATT_SMEM);

    // 1) qkv = x @ w_qkv^T    [8192, 2304]
    {
        dim3 grid(QKV_COLS / 128, (BATCH * SEQ) / 128);  // (18, 64)
        sgemm_nt<false><<<grid, 256>>>(x, w_qkv, nullptr, qkv,
                                       BATCH * SEQ, QKV_COLS, NDIM);
    }
    // 2) fused shuffled-Q attention -> att [8192, 768]
    {
        dim3 grid(SEQ / 64, BATCH * HEADS);  // (16, 96)
        attn_kernel<<<grid, 128, ATT_SMEM>>>(qkv, perms, att);
    }
    // 3) out = att @ w_out^T + b_out    [8192, 768]
    {
        dim3 grid(NDIM / 128, (BATCH * SEQ) / 128);  // (6, 64)
        sgemm_nt<true><<<grid, 256>>>(att, w_out, b_out, out,
                                      BATCH * SEQ, NDIM, NDIM);
    }
}

// round 3
// speedup vs baseline: 2.6896x; 2.6896x over previous
#include <cuda_runtime.h>
#include <cuda_bf16.h>
#include <cstdint>
#include <math.h>

#define BATCH 8
#define SEQ 1024
#define NDIM 768
#define HEADS 12
#define DHEAD 64
#define INNER 768
#define QKV_COLS 2304
#define ROWS_TOTAL (BATCH * SEQ)   // 8192

// ---------------------------------------------------------------------------
// Device scratch (no cudaMalloc allowed)
// ---------------------------------------------------------------------------
__device__ float g_qkv[ROWS_TOTAL * QKV_COLS];   // [8192, 2304] fp32
__device__ float g_att[ROWS_TOTAL * NDIM];       // [8192, 768] fp32

__device__ __nv_bfloat16 g_xhi[ROWS_TOTAL * NDIM];
__device__ __nv_bfloat16 g_xlo[ROWS_TOTAL * NDIM];
__device__ __nv_bfloat16 g_whi[QKV_COLS * NDIM];
__device__ __nv_bfloat16 g_wlo[QKV_COLS * NDIM];
__device__ __nv_bfloat16 g_ahi[ROWS_TOTAL * NDIM];
__device__ __nv_bfloat16 g_alo[ROWS_TOTAL * NDIM];
__device__ __nv_bfloat16 g_vhi[NDIM * NDIM];
__device__ __nv_bfloat16 g_vlo[NDIM * NDIM];

// ---------------------------------------------------------------------------
// Helpers (baseline PTX, valid on compute_103: mma.sync / ldmatrix / cp.async)
// ---------------------------------------------------------------------------
__device__ __forceinline__ uint32_t smem_u32(const void* p) {
    uint32_t a;
    asm("{ .reg .u64 t; cvta.to.shared.u64 t, %1; cvt.u32.u64 %0, t; }"
        : "=r"(a) : "l"(p));
    return a;
}

__device__ __forceinline__ uint32_t f2tf32(float f) {
    uint32_t u;
    asm("cvt.rna.tf32.f32 %0, %1;" : "=r"(u) : "f"(f));
    return u;
}

__device__ __forceinline__ void mma_bf16(float* c, const uint32_t* a,
                                         uint32_t b0, uint32_t b1) {
    asm volatile(
        "mma.sync.aligned.m16n8k16.row.col.f32.bf16.bf16.f32 "
        "{%0,%1,%2,%3},{%4,%5,%6,%7},{%8,%9},{%0,%1,%2,%3};"
        : "+f"(c[0]), "+f"(c[1]), "+f"(c[2]), "+f"(c[3])
        : "r"(a[0]), "r"(a[1]), "r"(a[2]), "r"(a[3]), "r"(b0), "r"(b1));
}

__device__ __forceinline__ void mma_tf32(float* c, const uint32_t* a,
                                         uint32_t b0, uint32_t b1) {
    asm volatile(
        "mma.sync.aligned.m16n8k8.row.col.f32.tf32.tf32.f32 "
        "{%0,%1,%2,%3},{%4,%5,%6,%7},{%8,%9},{%0,%1,%2,%3};"
        : "+f"(c[0]), "+f"(c[1]), "+f"(c[2]), "+f"(c[3])
        : "r"(a[0]), "r"(a[1]), "r"(a[2]), "r"(a[3]), "r"(b0), "r"(b1));
}

__device__ __forceinline__ void ldm4(uint32_t* a, uint32_t addr) {
    asm volatile("ldmatrix.sync.aligned.m8n8.x4.shared.b16 {%0,%1,%2,%3}, [%4];"
                 : "=r"(a[0]), "=r"(a[1]), "=r"(a[2]), "=r"(a[3]) : "r"(addr));
}

__device__ __forceinline__ void cp_async16(uint32_t dst, const void* src) {
    asm volatile("cp.async.cg.shared.global [%0], [%1], 16;" ::"r"(dst),
                 "l"(src));
}
#define CP_COMMIT() asm volatile("cp.async.commit_group;" ::: "memory")
#define CP_WAIT0() asm volatile("cp.async.wait_group 0;" ::: "memory")

// ---------------------------------------------------------------------------
// Conversion kernel: fp32 -> bf16 hi + bf16 lo (hi = rn(x), lo = rn(x - hi))
// ---------------------------------------------------------------------------
__global__ void __launch_bounds__(256) cvt_hilo(const float* __restrict__ src,
                                                __nv_bfloat16* __restrict__ hi,
                                                __nv_bfloat16* __restrict__ lo,
                                                int n4) {
    int i = blockIdx.x * blockDim.x + threadIdx.x;
    int stride = gridDim.x * blockDim.x;
    for (; i < n4; i += stride) {
        float4 v = ((const float4*)src)[i];
        __nv_bfloat16 h0 = __float2bfloat16(v.x);
        __nv_bfloat16 h1 = __float2bfloat16(v.y);
        __nv_bfloat16 h2 = __float2bfloat16(v.z);
        __nv_bfloat16 h3 = __float2bfloat16(v.w);
        __nv_bfloat16 l0 = __float2bfloat16(v.x - __bfloat162float(h0));
        __nv_bfloat16 l1 = __float2bfloat16(v.y - __bfloat162float(h1));
        __nv_bfloat16 l2 = __float2bfloat16(v.z - __bfloat162float(h2));
        __nv_bfloat16 l3 = __float2bfloat16(v.w - __bfloat162float(h3));
        __nv_bfloat162* hp = (__nv_bfloat162*)hi;
        __nv_bfloat162* lp = (__nv_bfloat162*)lo;
        __nv_bfloat162 a, b;
        a.x = h0; a.y = h1; b.x = h2; b.y = h3;
        hp[2 * i] = a; hp[2 * i + 1] = b;
        a.x = l0; a.y = l1; b.x = l2; b.y = l3;
        lp[2 * i] = a; lp[2 * i + 1] = b;
    }
}

// ---------------------------------------------------------------------------
// bf16x3 GEMM via mma.sync (NT): C[M,N] = A[M,K] @ B[N,K]^T (+ bias)
// 128x128 tile, BK=32, 256 threads (8 warps, each 32x64), cp.async dbl-buffer.
// smem tile: 128 rows x 40 bf16 (80B row stride, conflict-free fragments).
// ---------------------------------------------------------------------------
#define GK 32
#define TILE_B 10240        // 128 * 80
#define BUF_B (4 * TILE_B)  // Ahi | Alo | Bhi | Blo
#define GEMM_SMEM (2 * BUF_B)

template <bool HAS_BIAS>
__global__ void __launch_bounds__(256) gemm_bf16x3(
    const __nv_bfloat16* __restrict__ Ahi, const __nv_bfloat16* __restrict__ Alo,
    const __nv_bfloat16* __restrict__ Bhi, const __nv_bfloat16* __restrict__ Blo,
    const float* __restrict__ bias, float* __restrict__ C, int M, int N, int K) {
    extern __shared__ char gsm[];
    const uint32_t sbase = smem_u32(gsm);

    const int tid = threadIdx.x;
    const int w = tid >> 5, l = tid & 31;
    const int g = l >> 2, t4 = l & 3;
    const int bm = blockIdx.y * 128, bn = blockIdx.x * 128;
    const int mrow0 = (w & 3) * 32, ncol0 = (w >> 2) * 64;

    const __nv_bfloat16* tsrc[4] = {Ahi, Alo, Bhi, Blo};

    float acc[2][8][4];
#pragma unroll
    for (int mi = 0; mi < 2; mi++)
#pragma unroll
        for (int ni = 0; ni < 8; ni++)
#pragma unroll
            for (int q = 0; q < 4; q++) acc[mi][ni][q] = 0.f;

    // ldmatrix lane geometry
    const int arow = (l & 7) + ((l >> 3) & 1) * 8;
    const int acolb = ((l >> 4) & 1) * 16;

    auto load_chunk = [&](int c) {
        const int k0 = c * GK;
        const uint32_t db = sbase + (uint32_t)(c & 1) * BUF_B;
#pragma unroll
        for (int t = 0; t < 4; t++) {
            const __nv_bfloat16* src = tsrc[t];
            const int rb = (t < 2) ? bm : bn;
#pragma unroll
            for (int i = 0; i < 2; i++) {
                int u = tid + i * 256;
                int row = u >> 2, seg = u & 3;
                const void* gp = src + (size_t)(rb + row) * K + k0 + seg * 8;
                uint32_t sp = db + (uint32_t)(t * TILE_B + row * 80 + seg * 16);
                cp_async16(sp, gp);
            }
        }
        CP_COMMIT();
    };

    const int nchunk = K / GK;
    load_chunk(0);

    for (int c = 0; c < nchunk; c++) {
        CP_WAIT0();
        __syncthreads();
        if (c + 1 < nchunk) load_chunk(c + 1);

        const uint32_t bb = sbase + (uint32_t)(c & 1) * BUF_B;
        const char* bufc = gsm + (size_t)(c & 1) * BUF_B;
#pragma unroll
        for (int pass = 0; pass < 3; pass++) {
            const uint32_t At = bb + (pass == 2 ? TILE_B : 0);
            const int btile = (pass == 1) ? 3 : 2;
            const uint32_t* Bw = (const uint32_t*)(bufc + btile * TILE_B);
#pragma unroll
            for (int kc = 0; kc < 2; kc++) {
                uint32_t a[2][4];
                ldm4(a[0], At + (uint32_t)((mrow0 + arow) * 80 + kc * 32 + acolb));
                ldm4(a[1], At + (uint32_t)((mrow0 + 16 + arow) * 80 + kc * 32 + acolb));
#pragma unroll
                for (int ni = 0; ni < 8; ni++) {
                    int nrow = ncol0 + ni * 8 + g;
                    uint32_t b0 = Bw[nrow * 20 + kc * 8 + t4];
                    uint32_t b1 = Bw[nrow * 20 + kc * 8 + t4 + 4];
                    mma_bf16(acc[0][ni], a[0], b0, b1);
                    mma_bf16(acc[1][ni], a[1], b0, b1);
                }
            }
        }
    }

    // Epilogue
#pragma unroll
    for (int mi = 0; mi < 2; mi++) {
        const int r0 = bm + mrow0 + mi * 16 + g;
#pragma unroll
        for (int ni = 0; ni < 8; ni++) {
            const int col = bn + ncol0 + ni * 8 + 2 * t4;
            float b0v = 0.f, b1v = 0.f;
            if (HAS_BIAS) { b0v = bias[col]; b1v = bias[col + 1]; }
            float2 v0, v1;
            v0.x = acc[mi][ni][0] + b0v; v0.y = acc[mi][ni][1] + b1v;
            v1.x = acc[mi][ni][2] + b0v; v1.y = acc[mi][ni][3] + b1v;
            *(float2*)(C + (size_t)r0 * N + col) = v0;
            *(float2*)(C + (size_t)(r0 + 8) * N + col) = v1;
        }
    }
}

// ---------------------------------------------------------------------------
// Fused shuffled-Q flash attention via tf32 mma.sync.
// Block: 128 threads (4 warps), 64 q-rows per block, KV tiles of 64.
// Each warp owns 16 q-rows. All operands staged in smem as tf32.
// smem strides (words): Qs 68, Ks 68, Vs 72, Ps 68 (conflict-free frag loads).
// ---------------------------------------------------------------------------
#define AS_QS 0
#define AS_KS (64 * 68)
#define AS_VS (2 * 64 * 68)
#define AS_PS (AS_VS + 64 * 72)
#define ATT_WORDS (AS_PS + 64 * 68)
#define ATT_SMEM (ATT_WORDS * 4)

__global__ void __launch_bounds__(128) attn_kernel(const float* __restrict__ qkv,
                                                   const int* __restrict__ perms,
                                                   float* __restrict__ att_out) {
    extern __shared__ uint32_t sms[];

    const int bh = blockIdx.y;
    const int b = bh / HEADS;
    const int h = bh % HEADS;
    const int q0 = blockIdx.x * 64;

    const int tid = threadIdx.x;
    const int w = tid >> 5, l = tid & 31;
    const int g = l >> 2, t4 = l & 3;
    const int qr0 = w * 16;

    const float* qkv_b = qkv + (size_t)b * SEQ * QKV_COLS;
    const int hoff = h * DHEAD;

    // Gather permuted Q tile (scale folded, tf32-converted).
    const int* ph = perms + (size_t)h * (SEQ * DHEAD) + q0 * DHEAD;
#pragma unroll 4
    for (int it = 0; it < 32; it++) {
        int f = it * 128 + tid;
        int p = ph[f];
        int nn = p >> 6, dd = p & 63;
        int i = f >> 6, j = f & 63;
        sms[AS_QS + i * 68 + j] =
            f2tf32(qkv_b[(size_t)nn * QKV_COLS + hoff + dd] * 0.125f);
    }
    __syncthreads();

    // Preload Q fragments for all 8 k-chunks (register-resident).
    uint32_t qf[8][4];
#pragma unroll
    for (int kc = 0; kc < 8; kc++) {
        qf[kc][0] = sms[AS_QS + (qr0 + g) * 68 + kc * 8 + t4];
        qf[kc][1] = sms[AS_QS + (qr0 + g + 8) * 68 + kc * 8 + t4];
        qf[kc][2] = sms[AS_QS + (qr0 + g) * 68 + kc * 8 + t4 + 4];
        qf[kc][3] = sms[AS_QS + (qr0 + g + 8) * 68 + kc * 8 + t4 + 4];
    }

    float m0 = -1e30f, m1 = -1e30f, l0 = 0.f, l1 = 0.f;
    float O[8][4];
#pragma unroll
    for (int dt = 0; dt < 8; dt++)
#pragma unroll
        for (int q = 0; q < 4; q++) O[dt][q] = 0.f;

    for (int t = 0; t < 16; t++) {
        __syncthreads();  // prev tile's PV reads done
        const int kv0 = t * 64;
        // Load K, V tiles (tf32-converted) into smem.
#pragma unroll
        for (int it = 0; it < 8; it++) {
            int fi = it * 128 + tid;
            int row = fi >> 4;
            int c4 = (fi & 15) * 4;
            const float* bp = qkv_b + (size_t)(kv0 + row) * QKV_COLS + hoff + c4;
            float4 kk = *(const float4*)(bp + INNER);
            uint4 ku = make_uint4(f2tf32(kk.x), f2tf32(kk.y), f2tf32(kk.z),
                                  f2tf32(kk.w));
            *(uint4*)&sms[AS_KS + row * 68 + c4] = ku;
            float4 vv = *(const float4*)(bp + 2 * INNER);
            uint4 vu = make_uint4(f2tf32(vv.x), f2tf32(vv.y), f2tf32(vv.z),
                                  f2tf32(vv.w));
            *(uint4*)&sms[AS_VS + row * 72 + c4] = vu;
        }
        __syncthreads();

        // S = Q @ K^T   (per warp: 16 x 64)
        float S[8][4];
#pragma unroll
        for (int nt = 0; nt < 8; nt++)
#pragma unroll
            for (int q = 0; q < 4; q++) S[nt][q] = 0.f;
#pragma unroll
        for (int kc = 0; kc < 8; kc++) {
#pragma unroll
            for (int nt = 0; nt < 8; nt++) {
                uint32_t b0 = sms[AS_KS + (nt * 8 + g) * 68 + kc * 8 + t4];
                uint32_t b1 = sms[AS_KS + (nt * 8 + g) * 68 + kc * 8 + t4 + 4];
                mma_tf32(S[nt], qf[kc], b0, b1);
            }
        }

        // Online softmax (rows r0 = g, r1 = g+8 of warp tile).
        float mx0 = -1e30f, mx1 = -1e30f;
#pragma unroll
        for (int nt = 0; nt < 8; nt++) {
            mx0 = fmaxf(mx0, fmaxf(S[nt][0], S[nt][1]));
            mx1 = fmaxf(mx1, fmaxf(S[nt][2], S[nt][3]));
        }
        mx0 = fmaxf(mx0, __shfl_xor_sync(0xffffffffu, mx0, 1));
        mx0 = fmaxf(mx0, __shfl_xor_sync(0xffffffffu, mx0, 2));
        mx1 = fmaxf(mx1, __shfl_xor_sync(0xffffffffu, mx1, 1));
        mx1 = fmaxf(mx1, __shfl_xor_sync(0xffffffffu, mx1, 2));

        const float mn0 = fmaxf(m0, mx0);
        const float mn1 = fmaxf(m1, mx1);
        const float al0 = __expf(m0 - mn0);
        const float al1 = __expf(m1 - mn1);
        float sum0 = 0.f, sum1 = 0.f;
#pragma unroll
        for (int nt = 0; nt < 8; nt++) {
            S[nt][0] = __expf(S[nt][0] - mn0);
            S[nt][1] = __expf(S[nt][1] - mn0);
            S[nt][2] = __expf(S[nt][2] - mn1);
            S[nt][3] = __expf(S[nt][3] - mn1);
            sum0 += S[nt][0] + S[nt][1];
            sum1 += S[nt][2] + S[nt][3];
        }
        sum0 += __shfl_xor_sync(0xffffffffu, sum0, 1);
        sum0 += __shfl_xor_sync(0xffffffffu, sum0, 2);
        sum1 += __shfl_xor_sync(0xffffffffu, sum1, 1);
        sum1 += __shfl_xor_sync(0xffffffffu, sum1, 2);
        l0 = l0 * al0 + sum0;
        l1 = l1 * al1 + sum1;
        m0 = mn0; m1 = mn1;
#pragma unroll
        for (int dt = 0; dt < 8; dt++) {
            O[dt][0] *= al0; O[dt][1] *= al0;
            O[dt][2] *= al1; O[dt][3] *= al1;
        }

        // Stage P (tf32) in per-warp smem region.
#pragma unroll
        for (int nt = 0; nt < 8; nt++) {
            const int cw = nt * 8 + 2 * t4;
            sms[AS_PS + (qr0 + g) * 68 + cw] = f2tf32(S[nt][0]);
            sms[AS_PS + (qr0 + g) * 68 + cw + 1] = f2tf32(S[nt][1]);
            sms[AS_PS + (qr0 + g + 8) * 68 + cw] = f2tf32(S[nt][2]);
            sms[AS_PS + (qr0 + g + 8) * 68 + cw + 1] = f2tf32(S[nt][3]);
        }
        __syncwarp();

        // O += P @ V
#pragma unroll
        for (int kc = 0; kc < 8; kc++) {
            uint32_t a[4];
            a[0] = sms[AS_PS + (qr0 + g) * 68 + kc * 8 + t4];
            a[1] = sms[AS_PS + (qr0 + g + 8) * 68 + kc * 8 + t4];
            a[2] = sms[AS_PS + (qr0 + g) * 68 + kc * 8 + t4 + 4];
            a[3] = sms[AS_PS + (qr0 + g + 8) * 68 + kc * 8 + t4 + 4];
#pragma unroll
            for (int dt = 0; dt < 8; dt++) {
                uint32_t b0 = sms[AS_VS + (kc * 8 + t4) * 72 + dt * 8 + g];
                uint32_t b1 = sms[AS_VS + (kc * 8 + t4 + 4) * 72 + dt * 8 + g];
                mma_tf32(O[dt], a, b0, b1);
            }
        }
    }

    // Epilogue: normalize and write.
    const float inv0 = 1.0f / l0;
    const float inv1 = 1.0f / l1;
    float* orow0 = att_out + ((size_t)b * SEQ + q0 + qr0 + g) * NDIM + hoff;
    float* orow1 = orow0 + (size_t)8 * NDIM;
#pragma unroll
    for (int dt = 0; dt < 8; dt++) {
        float2 v0, v1;
        v0.x = O[dt][0] * inv0; v0.y = O[dt][1] * inv0;
        v1.x = O[dt][2] * inv1; v1.y = O[dt][3] * inv1;
        *(float2*)(orow0 + dt * 8 + 2 * t4) = v0;
        *(float2*)(orow1 + dt * 8 + 2 * t4) = v1;
    }
}

// ---------------------------------------------------------------------------
extern "C" void kernel_launch(void* const* d_in, const int* in_sizes, int n_in,
                              void* d_out, int out_size) {
    const float* x     = (const float*)d_in[0];
    const float* w_qkv = (const float*)d_in[1];
    const float* w_out = (const float*)d_in[2];
    const float* b_out = (const float*)d_in[3];
    const int*   perms = (const int*)d_in[4];
    float* out = (float*)d_out;

    float* qkv = nullptr;
    float* att = nullptr;
    cudaGetSymbolAddress((void**)&qkv, g_qkv);
    cudaGetSymbolAddress((void**)&att, g_att);
    __nv_bfloat16 *xhi, *xlo, *whi, *wlo, *ahi, *alo, *vhi, *vlo;
    cudaGetSymbolAddress((void**)&xhi, g_xhi);
    cudaGetSymbolAddress((void**)&xlo, g_xlo);
    cudaGetSymbolAddress((void**)&whi, g_whi);
    cudaGetSymbolAddress((void**)&wlo, g_wlo);
    cudaGetSymbolAddress((void**)&ahi, g_ahi);
    cudaGetSymbolAddress((void**)&alo, g_alo);
    cudaGetSymbolAddress((void**)&vhi, g_vhi);
    cudaGetSymbolAddress((void**)&vlo, g_vlo);

    cudaFuncSetAttribute(attn_kernel, cudaFuncAttributeMaxDynamicSharedMemorySize,
                         ATT_SMEM);
    cudaFuncSetAttribute(gemm_bf16x3<false>,
                         cudaFuncAttributeMaxDynamicSharedMemorySize, GEMM_SMEM);
    cudaFuncSetAttribute(gemm_bf16x3<true>,
                         cudaFuncAttributeMaxDynamicSharedMemorySize, GEMM_SMEM);

    // 1) split x and w_qkv into bf16 hi/lo
    {
        int n4 = ROWS_TOTAL * NDIM / 4;
        cvt_hilo<<<2048, 256>>>(x, xhi, xlo, n4);
        int m4 = QKV_COLS * NDIM / 4;
        cvt_hilo<<<1024, 256>>>(w_qkv, whi, wlo, m4);
    }
    // 2) qkv = x @ w_qkv^T  (bf16x3 mma.sync)
    {
        dim3 grid(QKV_COLS / 128, ROWS_TOTAL / 128);  // (18, 64)
        gemm_bf16x3<false><<<grid, 256, GEMM_SMEM>>>(xhi, xlo, whi, wlo, nullptr,
                                                     qkv, ROWS_TOTAL, QKV_COLS,
                                                     NDIM);
    }
    // 3) fused shuffled-Q attention (tf32 mma.sync) -> att
    {
        dim3 grid(SEQ / 64, BATCH * HEADS);  // (16, 96)
        attn_kernel<<<grid, 128, ATT_SMEM>>>(qkv, perms, att);
    }
    // 4) split att and w_out
    {
        int n4 = ROWS_TOTAL * NDIM / 4;
        cvt_hilo<<<2048, 256>>>(att, ahi, alo, n4);
        int m4 = NDIM * NDIM / 4;
        cvt_hilo<<<576, 256>>>(w_out, vhi, vlo, m4);
    }
    // 5) out = att @ w_out^T + b_out  (bf16x3 mma.sync)
    {
        dim3 grid(NDIM / 128, ROWS_TOTAL / 128);  // (6, 64)
        gemm_bf16x3<true><<<grid, 256, GEMM_SMEM>>>(ahi, alo, vhi, vlo, b_out,
                                                    out, ROWS_TOTAL, NDIM, NDIM);
    }
}

// round 4
// speedup vs baseline: 3.1205x; 1.1602x over previous
#include <cuda_runtime.h>
#include <cuda_bf16.h>
#include <cstdint>
#include <math.h>

#define BATCH 8
#define SEQ 1024
#define NDIM 768
#define HEADS 12
#define DHEAD 64
#define INNER 768
#define QKV_COLS 2304
#define ROWS_TOTAL (BATCH * SEQ)   // 8192

// ---------------------------------------------------------------------------
// Device scratch (no cudaMalloc allowed)
// ---------------------------------------------------------------------------
__device__ float g_qkv[ROWS_TOTAL * QKV_COLS];   // [8192, 2304] fp32 (tf32-rounded)
__device__ float g_att[ROWS_TOTAL * NDIM];       // [8192, 768] fp32

__device__ __nv_bfloat16 g_xhi[ROWS_TOTAL * NDIM];
__device__ __nv_bfloat16 g_xlo[ROWS_TOTAL * NDIM];
__device__ __nv_bfloat16 g_whi[QKV_COLS * NDIM];
__device__ __nv_bfloat16 g_wlo[QKV_COLS * NDIM];
__device__ __nv_bfloat16 g_ahi[ROWS_TOTAL * NDIM];
__device__ __nv_bfloat16 g_alo[ROWS_TOTAL * NDIM];
__device__ __nv_bfloat16 g_vhi[NDIM * NDIM];
__device__ __nv_bfloat16 g_vlo[NDIM * NDIM];

// ---------------------------------------------------------------------------
// Helpers (baseline PTX, valid on compute_103)
// ---------------------------------------------------------------------------
__device__ __forceinline__ uint32_t smem_u32(const void* p) {
    uint32_t a;
    asm("{ .reg .u64 t; cvta.to.shared.u64 t, %1; cvt.u32.u64 %0, t; }"
        : "=r"(a) : "l"(p));
    return a;
}

__device__ __forceinline__ uint32_t f2tf32(float f) {
    uint32_t u;
    asm("cvt.rna.tf32.f32 %0, %1;" : "=r"(u) : "f"(f));
    return u;
}

__device__ __forceinline__ void mma_bf16(float* c, const uint32_t* a,
                                         uint32_t b0, uint32_t b1) {
    asm volatile(
        "mma.sync.aligned.m16n8k16.row.col.f32.bf16.bf16.f32 "
        "{%0,%1,%2,%3},{%4,%5,%6,%7},{%8,%9},{%0,%1,%2,%3};"
        : "+f"(c[0]), "+f"(c[1]), "+f"(c[2]), "+f"(c[3])
        : "r"(a[0]), "r"(a[1]), "r"(a[2]), "r"(a[3]), "r"(b0), "r"(b1));
}

__device__ __forceinline__ void mma_tf32(float* c, const uint32_t* a,
                                         uint32_t b0, uint32_t b1) {
    asm volatile(
        "mma.sync.aligned.m16n8k8.row.col.f32.tf32.tf32.f32 "
        "{%0,%1,%2,%3},{%4,%5,%6,%7},{%8,%9},{%0,%1,%2,%3};"
        : "+f"(c[0]), "+f"(c[1]), "+f"(c[2]), "+f"(c[3])
        : "r"(a[0]), "r"(a[1]), "r"(a[2]), "r"(a[3]), "r"(b0), "r"(b1));
}

__device__ __forceinline__ void ldm4(uint32_t* a, uint32_t addr) {
    asm volatile("ldmatrix.sync.aligned.m8n8.x4.shared.b16 {%0,%1,%2,%3}, [%4];"
                 : "=r"(a[0]), "=r"(a[1]), "=r"(a[2]), "=r"(a[3]) : "r"(addr));
}

__device__ __forceinline__ void cp_async16(uint32_t dst, const void* src) {
    asm volatile("cp.async.cg.shared.global [%0], [%1], 16;" ::"r"(dst),
                 "l"(src));
}
#define CP_COMMIT() asm volatile("cp.async.commit_group;" ::: "memory")
#define CP_WAIT0() asm volatile("cp.async.wait_group 0;" ::: "memory")
#define CP_WAIT1() asm volatile("cp.async.wait_group 1;" ::: "memory")

// ---------------------------------------------------------------------------
// Conversion kernel: fp32 -> bf16 hi + bf16 lo
// ---------------------------------------------------------------------------
__global__ void __launch_bounds__(256) cvt_hilo(const float* __restrict__ src,
                                                __nv_bfloat16* __restrict__ hi,
                                                __nv_bfloat16* __restrict__ lo,
                                                int n4) {
    int i = blockIdx.x * blockDim.x + threadIdx.x;
    int stride = gridDim.x * blockDim.x;
    for (; i < n4; i += stride) {
        float4 v = ((const float4*)src)[i];
        __nv_bfloat16 h0 = __float2bfloat16(v.x);
        __nv_bfloat16 h1 = __float2bfloat16(v.y);
        __nv_bfloat16 h2 = __float2bfloat16(v.z);
        __nv_bfloat16 h3 = __float2bfloat16(v.w);
        __nv_bfloat16 l0 = __float2bfloat16(v.x - __bfloat162float(h0));
        __nv_bfloat16 l1 = __float2bfloat16(v.y - __bfloat162float(h1));
        __nv_bfloat16 l2 = __float2bfloat16(v.z - __bfloat162float(h2));
        __nv_bfloat16 l3 = __float2bfloat16(v.w - __bfloat162float(h3));
        __nv_bfloat162* hp = (__nv_bfloat162*)hi;
        __nv_bfloat162* lp = (__nv_bfloat162*)lo;
        __nv_bfloat162 a, b;
        a.x = h0; a.y = h1; b.x = h2; b.y = h3;
        hp[2 * i] = a; hp[2 * i + 1] = b;
        a.x = l0; a.y = l1; b.x = l2; b.y = l3;
        lp[2 * i] = a; lp[2 * i + 1] = b;
    }
}

// ---------------------------------------------------------------------------
// bf16x3 GEMM via mma.sync (NT): C = A @ B^T (+bias) (optional tf32 rounding)
// ---------------------------------------------------------------------------
#define GK 32
#define TILE_B 10240        // 128 * 80
#define BUF_B (4 * TILE_B)
#define GEMM_SMEM (2 * BUF_B)

template <bool HAS_BIAS, bool ROUND_TF32>
__global__ void __launch_bounds__(256) gemm_bf16x3(
    const __nv_bfloat16* __restrict__ Ahi, const __nv_bfloat16* __restrict__ Alo,
    const __nv_bfloat16* __restrict__ Bhi, const __nv_bfloat16* __restrict__ Blo,
    const float* __restrict__ bias, float* __restrict__ C, int M, int N, int K) {
    extern __shared__ char gsm[];
    const uint32_t sbase = smem_u32(gsm);

    const int tid = threadIdx.x;
    const int w = tid >> 5, l = tid & 31;
    const int g = l >> 2, t4 = l & 3;
    const int bm = blockIdx.y * 128, bn = blockIdx.x * 128;
    const int mrow0 = (w & 3) * 32, ncol0 = (w >> 2) * 64;

    const __nv_bfloat16* tsrc[4] = {Ahi, Alo, Bhi, Blo};

    float acc[2][8][4];
#pragma unroll
    for (int mi = 0; mi < 2; mi++)
#pragma unroll
        for (int ni = 0; ni < 8; ni++)
#pragma unroll
            for (int q = 0; q < 4; q++) acc[mi][ni][q] = 0.f;

    const int arow = (l & 7) + ((l >> 3) & 1) * 8;
    const int acolb = ((l >> 4) & 1) * 16;

    auto load_chunk = [&](int c) {
        const int k0 = c * GK;
        const uint32_t db = sbase + (uint32_t)(c & 1) * BUF_B;
#pragma unroll
        for (int t = 0; t < 4; t++) {
            const __nv_bfloat16* src = tsrc[t];
            const int rb = (t < 2) ? bm : bn;
#pragma unroll
            for (int i = 0; i < 2; i++) {
                int u = tid + i * 256;
                int row = u >> 2, seg = u & 3;
                const void* gp = src + (size_t)(rb + row) * K + k0 + seg * 8;
                uint32_t sp = db + (uint32_t)(t * TILE_B + row * 80 + seg * 16);
                cp_async16(sp, gp);
            }
        }
        CP_COMMIT();
    };

    const int nchunk = K / GK;
    load_chunk(0);

    for (int c = 0; c < nchunk; c++) {
        CP_WAIT0();
        __syncthreads();
        if (c + 1 < nchunk) load_chunk(c + 1);

        const uint32_t bb = sbase + (uint32_t)(c & 1) * BUF_B;
        const char* bufc = gsm + (size_t)(c & 1) * BUF_B;
#pragma unroll
        for (int pass = 0; pass < 3; pass++) {
            const uint32_t At = bb + (pass == 2 ? TILE_B : 0);
            const int btile = (pass == 1) ? 3 : 2;
            const uint32_t* Bw = (const uint32_t*)(bufc + btile * TILE_B);
#pragma unroll
            for (int kc = 0; kc < 2; kc++) {
                uint32_t a[2][4];
                ldm4(a[0], At + (uint32_t)((mrow0 + arow) * 80 + kc * 32 + acolb));
                ldm4(a[1], At + (uint32_t)((mrow0 + 16 + arow) * 80 + kc * 32 + acolb));
#pragma unroll
                for (int ni = 0; ni < 8; ni++) {
                    int nrow = ncol0 + ni * 8 + g;
                    uint32_t b0 = Bw[nrow * 20 + kc * 8 + t4];
                    uint32_t b1 = Bw[nrow * 20 + kc * 8 + t4 + 4];
                    mma_bf16(acc[0][ni], a[0], b0, b1);
                    mma_bf16(acc[1][ni], a[1], b0, b1);
                }
            }
        }
    }

#pragma unroll
    for (int mi = 0; mi < 2; mi++) {
        const int r0 = bm + mrow0 + mi * 16 + g;
#pragma unroll
        for (int ni = 0; ni < 8; ni++) {
            const int col = bn + ncol0 + ni * 8 + 2 * t4;
            float b0v = 0.f, b1v = 0.f;
            if (HAS_BIAS) { b0v = bias[col]; b1v = bias[col + 1]; }
            float vals[4];
            vals[0] = acc[mi][ni][0] + b0v; vals[1] = acc[mi][ni][1] + b1v;
            vals[2] = acc[mi][ni][2] + b0v; vals[3] = acc[mi][ni][3] + b1v;
            if (ROUND_TF32) {
#pragma unroll
                for (int q = 0; q < 4; q++)
                    vals[q] = __uint_as_float(f2tf32(vals[q]));
            }
            float2 v0, v1;
            v0.x = vals[0]; v0.y = vals[1];
            v1.x = vals[2]; v1.y = vals[3];
            *(float2*)(C + (size_t)r0 * N + col) = v0;
            *(float2*)(C + (size_t)(r0 + 8) * N + col) = v1;
        }
    }
}

// ---------------------------------------------------------------------------
// Fused shuffled-Q flash attention v2 (tf32 mma.sync).
// 256 threads (8 warps), 128 q-rows/block, KV tiles of 64, cp.async dbl-buffer.
// smem: two 8960-word buffers. Buf layout: K[64][68] | V[64][72].
// Buf1 initially holds Q[128][70] (freed after fragment preload).
// qkv values are pre-rounded to tf32 by GEMM1's epilogue.
// ---------------------------------------------------------------------------
#define KSTR 68
#define VSTR 72
#define QSTR 70
#define KVBUF 8960                    // words: 64*68 + 64*72
#define VOFF 4352                     // words: 64*68
#define ATT_SMEM (2 * KVBUF * 4)      // 71680 bytes

__global__ void __launch_bounds__(256, 2) attn_kernel(
    const float* __restrict__ qkv, const int* __restrict__ perms,
    float* __restrict__ att_out) {
    extern __shared__ uint32_t sms[];
    const uint32_t sbase = smem_u32(sms);

    const int bh = blockIdx.y;
    const int b = bh / HEADS;
    const int h = bh % HEADS;
    const int q0 = blockIdx.x * 128;

    const int tid = threadIdx.x;
    const int w = tid >> 5, l = tid & 31;
    const int g = l >> 2, t4 = l & 3;
    const int qr0 = w * 16;

    const float* qkv_b = qkv + (size_t)b * SEQ * QKV_COLS;
    const int hoff = h * DHEAD;

    const int cp_row = tid >> 4;          // 0..15
    const int cp_seg = (tid & 15) * 4;    // float offset, 16B units

    auto issue_kv = [&](int t, int bsel) {
        const int kv0 = t * 64;
        const float* kb = qkv_b + (size_t)kv0 * QKV_COLS + hoff + INNER + cp_seg;
        const float* vb = kb + INNER;
        const uint32_t kd = sbase + (uint32_t)(bsel * KVBUF) * 4;
#pragma unroll
        for (int i = 0; i < 4; i++) {
            const int row = cp_row + i * 16;
            cp_async16(kd + (uint32_t)(row * KSTR + cp_seg) * 4,
                       kb + (size_t)row * QKV_COLS);
        }
#pragma unroll
        for (int i = 0; i < 4; i++) {
            const int row = cp_row + i * 16;
            cp_async16(kd + (uint32_t)(VOFF + row * VSTR + cp_seg) * 4,
                       vb + (size_t)row * QKV_COLS);
        }
        CP_COMMIT();
    };

    // Kick off tile 0 into buf0, then gather Q into buf1 (overlapped).
    issue_kv(0, 0);

    const int* ph = perms + (size_t)h * (SEQ * DHEAD) + q0 * DHEAD;
#pragma unroll 4
    for (int it = 0; it < 32; it++) {
        int f = it * 256 + tid;
        int p = ph[f];
        int nn = p >> 6, dd = p & 63;
        int i = f >> 6, j = f & 63;
        sms[KVBUF + i * QSTR + j] =
            f2tf32(qkv_b[(size_t)nn * QKV_COLS + hoff + dd] * 0.125f);
    }
    __syncthreads();

    // Preload Q fragments for all 8 k-chunks (register-resident).
    uint32_t qf[8][4];
#pragma unroll
    for (int kc = 0; kc < 8; kc++) {
        qf[kc][0] = sms[KVBUF + (qr0 + g) * QSTR + kc * 8 + t4];
        qf[kc][1] = sms[KVBUF + (qr0 + g + 8) * QSTR + kc * 8 + t4];
        qf[kc][2] = sms[KVBUF + (qr0 + g) * QSTR + kc * 8 + t4 + 4];
        qf[kc][3] = sms[KVBUF + (qr0 + g + 8) * QSTR + kc * 8 + t4 + 4];
    }
    __syncthreads();   // buf1 now free for tile 1

    float m0 = -1e30f, m1 = -1e30f, l0 = 0.f, l1 = 0.f;
    float O[8][4];
#pragma unroll
    for (int dt = 0; dt < 8; dt++)
#pragma unroll
        for (int q = 0; q < 4; q++) O[dt][q] = 0.f;

    const int srcA = (l & 28) | (t4 >> 1);
    const int srcB = srcA | 2;
    const bool lo = (t4 & 1) != 0;

    for (int t = 0; t < 16; t++) {
        if (t < 15) {
            issue_kv(t + 1, (t + 1) & 1);
            CP_WAIT1();
        } else {
            CP_WAIT0();
        }
        __syncthreads();   // tile t data visible to all warps

        const uint32_t kw = (uint32_t)(t & 1) * KVBUF;
        const uint32_t vw = kw + VOFF;

        // S = Q @ K^T (per warp: 16 x 64)
        float S[8][4];
#pragma unroll
        for (int nt = 0; nt < 8; nt++)
#pragma unroll
            for (int q = 0; q < 4; q++) S[nt][q] = 0.f;
#pragma unroll
        for (int kc = 0; kc < 8; kc++) {
#pragma unroll
            for (int nt = 0; nt < 8; nt++) {
                uint32_t b0 = sms[kw + (nt * 8 + g) * KSTR + kc * 8 + t4];
                uint32_t b1 = sms[kw + (nt * 8 + g) * KSTR + kc * 8 + t4 + 4];
                mma_tf32(S[nt], qf[kc], b0, b1);
            }
        }

        // Online softmax (rows g and g+8 of this warp's 16-row tile).
        float mx0 = -1e30f, mx1 = -1e30f;
#pragma unroll
        for (int nt = 0; nt < 8; nt++) {
            mx0 = fmaxf(mx0, fmaxf(S[nt][0], S[nt][1]));
            mx1 = fmaxf(mx1, fmaxf(S[nt][2], S[nt][3]));
        }
        mx0 = fmaxf(mx0, __shfl_xor_sync(0xffffffffu, mx0, 1));
        mx0 = fmaxf(mx0, __shfl_xor_sync(0xffffffffu, mx0, 2));
        mx1 = fmaxf(mx1, __shfl_xor_sync(0xffffffffu, mx1, 1));
        mx1 = fmaxf(mx1, __shfl_xor_sync(0xffffffffu, mx1, 2));

        const float mn0 = fmaxf(m0, mx0);
        const float mn1 = fmaxf(m1, mx1);
        const float al0 = __expf(m0 - mn0);
        const float al1 = __expf(m1 - mn1);
        float sum0 = 0.f, sum1 = 0.f;
#pragma unroll
        for (int nt = 0; nt < 8; nt++) {
            S[nt][0] = __expf(S[nt][0] - mn0);
            S[nt][1] = __expf(S[nt][1] - mn0);
            S[nt][2] = __expf(S[nt][2] - mn1);
            S[nt][3] = __expf(S[nt][3] - mn1);
            sum0 += S[nt][0] + S[nt][1];
            sum1 += S[nt][2] + S[nt][3];
        }
        sum0 += __shfl_xor_sync(0xffffffffu, sum0, 1);
        sum0 += __shfl_xor_sync(0xffffffffu, sum0, 2);
        sum1 += __shfl_xor_sync(0xffffffffu, sum1, 1);
        sum1 += __shfl_xor_sync(0xffffffffu, sum1, 2);
        l0 = l0 * al0 + sum0;
        l1 = l1 * al1 + sum1;
        m0 = mn0; m1 = mn1;
#pragma unroll
        for (int dt = 0; dt < 8; dt++) {
            O[dt][0] *= al0; O[dt][1] *= al0;
            O[dt][2] *= al1; O[dt][3] *= al1;
        }

        // O += P @ V.  P fragments built via warp shuffles (no smem).
#pragma unroll
        for (int kc = 0; kc < 8; kc++) {
            uint32_t p0 = f2tf32(S[kc][0]);
            uint32_t p1 = f2tf32(S[kc][1]);
            uint32_t p2 = f2tf32(S[kc][2]);
            uint32_t p3 = f2tf32(S[kc][3]);
            uint32_t v00 = __shfl_sync(0xffffffffu, p0, srcA);
            uint32_t v01 = __shfl_sync(0xffffffffu, p1, srcA);
            uint32_t v10 = __shfl_sync(0xffffffffu, p2, srcA);
            uint32_t v11 = __shfl_sync(0xffffffffu, p3, srcA);
            uint32_t w00 = __shfl_sync(0xffffffffu, p0, srcB);
            uint32_t w01 = __shfl_sync(0xffffffffu, p1, srcB);
            uint32_t w10 = __shfl_sync(0xffffffffu, p2, srcB);
            uint32_t w11 = __shfl_sync(0xffffffffu, p3, srcB);
            uint32_t a[4];
            a[0] = lo ? v01 : v00;
            a[1] = lo ? v11 : v10;
            a[2] = lo ? w01 : w00;
            a[3] = lo ? w11 : w10;
#pragma unroll
            for (int dt = 0; dt < 8; dt++) {
                uint32_t b0 = sms[vw + (kc * 8 + t4) * VSTR + dt * 8 + g];
                uint32_t b1 = sms[vw + (kc * 8 + t4 + 4) * VSTR + dt * 8 + g];
                mma_tf32(O[dt], a, b0, b1);
            }
        }
        __syncthreads();   // all warps done reading buf(t&1)
    }

    // Epilogue: normalize and write.
    const float inv0 = 1.0f / l0;
    const float inv1 = 1.0f / l1;
    float* orow0 = att_out + ((size_t)b * SEQ + q0 + qr0 + g) * NDIM + hoff;
    float* orow1 = orow0 + (size_t)8 * NDIM;
#pragma unroll
    for (int dt = 0; dt < 8; dt++) {
        float2 v0, v1;
        v0.x = O[dt][0] * inv0; v0.y = O[dt][1] * inv0;
        v1.x = O[dt][2] * inv1; v1.y = O[dt][3] * inv1;
        *(float2*)(orow0 + dt * 8 + 2 * t4) = v0;
        *(float2*)(orow1 + dt * 8 + 2 * t4) = v1;
    }
}

// ---------------------------------------------------------------------------
extern "C" void kernel_launch(void* const* d_in, const int* in_sizes, int n_in,
                              void* d_out, int out_size) {
    const float* x     = (const float*)d_in[0];
    const float* w_qkv = (const float*)d_in[1];
    const float* w_out = (const float*)d_in[2];
    const float* b_out = (const float*)d_in[3];
    const int*   perms = (const int*)d_in[4];
    float* out = (float*)d_out;

    float* qkv = nullptr;
    float* att = nullptr;
    cudaGetSymbolAddress((void**)&qkv, g_qkv);
    cudaGetSymbolAddress((void**)&att, g_att);
    __nv_bfloat16 *xhi, *xlo, *whi, *wlo, *ahi, *alo, *vhi, *vlo;
    cudaGetSymbolAddress((void**)&xhi, g_xhi);
    cudaGetSymbolAddress((void**)&xlo, g_xlo);
    cudaGetSymbolAddress((void**)&whi, g_whi);
    cudaGetSymbolAddress((void**)&wlo, g_wlo);
    cudaGetSymbolAddress((void**)&ahi, g_ahi);
    cudaGetSymbolAddress((void**)&alo, g_alo);
    cudaGetSymbolAddress((void**)&vhi, g_vhi);
    cudaGetSymbolAddress((void**)&vlo, g_vlo);

    cudaFuncSetAttribute(attn_kernel, cudaFuncAttributeMaxDynamicSharedMemorySize,
                         ATT_SMEM);
    cudaFuncSetAttribute((const void*)gemm_bf16x3<false, true>,
                         cudaFuncAttributeMaxDynamicSharedMemorySize, GEMM_SMEM);
    cudaFuncSetAttribute((const void*)gemm_bf16x3<true, false>,
                         cudaFuncAttributeMaxDynamicSharedMemorySize, GEMM_SMEM);

    // 1) split x and w_qkv into bf16 hi/lo
    {
        int n4 = ROWS_TOTAL * NDIM / 4;
        cvt_hilo<<<2048, 256>>>(x, xhi, xlo, n4);
        int m4 = QKV_COLS * NDIM / 4;
        cvt_hilo<<<1024, 256>>>(w_qkv, whi, wlo, m4);
    }
    // 2) qkv = x @ w_qkv^T  (bf16x3 mma.sync, epilogue rounds to tf32)
    {
        dim3 grid(QKV_COLS / 128, ROWS_TOTAL / 128);  // (18, 64)
        gemm_bf16x3<false, true><<<grid, 256, GEMM_SMEM>>>(
            xhi, xlo, whi, wlo, nullptr, qkv, ROWS_TOTAL, QKV_COLS, NDIM);
    }
    // 3) fused shuffled-Q attention (tf32 mma.sync) -> att
    {
        dim3 grid(SEQ / 128, BATCH * HEADS);  // (8, 96)
        attn_kernel<<<grid, 256, ATT_SMEM>>>(qkv, perms, att);
    }
    // 4) split att and w_out
    {
        int n4 = ROWS_TOTAL * NDIM / 4;
        cvt_hilo<<<2048, 256>>>(att, ahi, alo, n4);
        int m4 = NDIM * NDIM / 4;
        cvt_hilo<<<576, 256>>>(w_out, vhi, vlo, m4);
    }
    // 5) out = att @ w_out^T + b_out  (bf16x3 mma.sync)
    {
        dim3 grid(NDIM / 128, ROWS_TOTAL / 128);  // (6, 64)
        gemm_bf16x3<true, false><<<grid, 256, GEMM_SMEM>>>(
            ahi, alo, vhi, vlo, b_out, out, ROWS_TOTAL, NDIM, NDIM);
    }
}

// round 6
// speedup vs baseline: 3.2464x; 1.0403x over previous
#include <cuda_runtime.h>
#include <cuda_bf16.h>
#include <cstdint>
#include <math.h>

#define BATCH 8
#define SEQ 1024
#define NDIM 768
#define HEADS 12
#define DHEAD 64
#define INNER 768
#define QKV_COLS 2304
#define ROWS_TOTAL (BATCH * SEQ)   // 8192

// ---------------------------------------------------------------------------
// Device scratch (no cudaMalloc allowed)
// ---------------------------------------------------------------------------
__device__ float g_qkv[ROWS_TOTAL * QKV_COLS];   // [8192, 2304] fp32 (tf32-rounded)

__device__ __nv_bfloat16 g_xhi[ROWS_TOTAL * NDIM];
__device__ __nv_bfloat16 g_xlo[ROWS_TOTAL * NDIM];
__device__ __nv_bfloat16 g_whi[QKV_COLS * NDIM];
__device__ __nv_bfloat16 g_wlo[QKV_COLS * NDIM];
__device__ __nv_bfloat16 g_ahi[ROWS_TOTAL * NDIM];   // attention out hi
__device__ __nv_bfloat16 g_alo[ROWS_TOTAL * NDIM];   // attention out lo
__device__ __nv_bfloat16 g_vhi[NDIM * NDIM];
__device__ __nv_bfloat16 g_vlo[NDIM * NDIM];

// ---------------------------------------------------------------------------
// Helpers (baseline PTX, valid on compute_103)
// ---------------------------------------------------------------------------
__device__ __forceinline__ uint32_t smem_u32(const void* p) {
    uint32_t a;
    asm("{ .reg .u64 t; cvta.to.shared.u64 t, %1; cvt.u32.u64 %0, t; }"
        : "=r"(a) : "l"(p));
    return a;
}

__device__ __forceinline__ uint32_t f2tf32(float f) {
    uint32_t u;
    asm("cvt.rna.tf32.f32 %0, %1;" : "=r"(u) : "f"(f));
    return u;
}

__device__ __forceinline__ void mma_bf16(float* c, const uint32_t* a,
                                         uint32_t b0, uint32_t b1) {
    asm volatile(
        "mma.sync.aligned.m16n8k16.row.col.f32.bf16.bf16.f32 "
        "{%0,%1,%2,%3},{%4,%5,%6,%7},{%8,%9},{%0,%1,%2,%3};"
        : "+f"(c[0]), "+f"(c[1]), "+f"(c[2]), "+f"(c[3])
        : "r"(a[0]), "r"(a[1]), "r"(a[2]), "r"(a[3]), "r"(b0), "r"(b1));
}

__device__ __forceinline__ void mma_tf32(float* c, const uint32_t* a,
                                         uint32_t b0, uint32_t b1) {
    asm volatile(
        "mma.sync.aligned.m16n8k8.row.col.f32.tf32.tf32.f32 "
        "{%0,%1,%2,%3},{%4,%5,%6,%7},{%8,%9},{%0,%1,%2,%3};"
        : "+f"(c[0]), "+f"(c[1]), "+f"(c[2]), "+f"(c[3])
        : "r"(a[0]), "r"(a[1]), "r"(a[2]), "r"(a[3]), "r"(b0), "r"(b1));
}

__device__ __forceinline__ void ldm4(uint32_t* a, uint32_t addr) {
    asm volatile("ldmatrix.sync.aligned.m8n8.x4.shared.b16 {%0,%1,%2,%3}, [%4];"
                 : "=r"(a[0]), "=r"(a[1]), "=r"(a[2]), "=r"(a[3]) : "r"(addr));
}

__device__ __forceinline__ void cp_async16(uint32_t dst, const void* src) {
    asm volatile("cp.async.cg.shared.global [%0], [%1], 16;" ::"r"(dst),
                 "l"(src));
}
#define CP_COMMIT() asm volatile("cp.async.commit_group;" ::: "memory")
#define CP_WAIT0() asm volatile("cp.async.wait_group 0;" ::: "memory")
#define CP_WAIT1() asm volatile("cp.async.wait_group 1;" ::: "memory")

// ---------------------------------------------------------------------------
// Conversion kernel: fp32 -> bf16 hi + bf16 lo
// ---------------------------------------------------------------------------
__global__ void __launch_bounds__(256) cvt_hilo(const float* __restrict__ src,
                                                __nv_bfloat16* __restrict__ hi,
                                                __nv_bfloat16* __restrict__ lo,
                                                int n4) {
    int i = blockIdx.x * blockDim.x + threadIdx.x;
    int stride = gridDim.x * blockDim.x;
    for (; i < n4; i += stride) {
        float4 v = ((const float4*)src)[i];
        __nv_bfloat16 h0 = __float2bfloat16(v.x);
        __nv_bfloat16 h1 = __float2bfloat16(v.y);
        __nv_bfloat16 h2 = __float2bfloat16(v.z);
        __nv_bfloat16 h3 = __float2bfloat16(v.w);
        __nv_bfloat16 l0 = __float2bfloat16(v.x - __bfloat162float(h0));
        __nv_bfloat16 l1 = __float2bfloat16(v.y - __bfloat162float(h1));
        __nv_bfloat16 l2 = __float2bfloat16(v.z - __bfloat162float(h2));
        __nv_bfloat16 l3 = __float2bfloat16(v.w - __bfloat162float(h3));
        __nv_bfloat162* hp = (__nv_bfloat162*)hi;
        __nv_bfloat162* lp = (__nv_bfloat162*)lo;
        __nv_bfloat162 a, b;
        a.x = h0; a.y = h1; b.x = h2; b.y = h3;
        hp[2 * i] = a; hp[2 * i + 1] = b;
        a.x = l0; a.y = l1; b.x = l2; b.y = l3;
        lp[2 * i] = a; lp[2 * i + 1] = b;
    }
}

// ---------------------------------------------------------------------------
// bf16x3 GEMM via mma.sync (NT): C = A @ B^T (+bias) (optional tf32 rounding)
// 128x128 tile, BK=32, 256 threads (8 warps, 32x64 each), cp.async dbl-buffer.
// A and B fragments via ldmatrix.x4. With the shared address pattern the four
// 8x8 sub-matrices land as {r0-7/k0-7, r8-15/k0-7, r0-7/k8-15, r8-15/k8-15}:
// A uses frags in order (0,1,2,3); B needs (0,2) then (1,3).
// ---------------------------------------------------------------------------
#define GK 32
#define TILE_B 10240        // 128 rows * 80 bytes
#define BUF_B (4 * TILE_B)  // Ahi | Alo | Bhi | Blo
#define GEMM_SMEM (2 * BUF_B)

template <bool HAS_BIAS, bool ROUND_TF32>
__global__ void __launch_bounds__(256) gemm_bf16x3(
    const __nv_bfloat16* __restrict__ Ahi, const __nv_bfloat16* __restrict__ Alo,
    const __nv_bfloat16* __restrict__ Bhi, const __nv_bfloat16* __restrict__ Blo,
    const float* __restrict__ bias, float* __restrict__ C, int M, int N, int K) {
    extern __shared__ char gsm[];
    const uint32_t sbase = smem_u32(gsm);

    const int tid = threadIdx.x;
    const int w = tid >> 5, l = tid & 31;
    const int g = l >> 2, t4 = l & 3;
    const int bm = blockIdx.y * 128, bn = blockIdx.x * 128;
    const int mrow0 = (w & 3) * 32, ncol0 = (w >> 2) * 64;

    const __nv_bfloat16* tsrc[4] = {Ahi, Alo, Bhi, Blo};

    float acc[2][8][4];
#pragma unroll
    for (int mi = 0; mi < 2; mi++)
#pragma unroll
        for (int ni = 0; ni < 8; ni++)
#pragma unroll
            for (int q = 0; q < 4; q++) acc[mi][ni][q] = 0.f;

    // ldmatrix lane geometry (shared by A and B fragment loads)
    const int arow = (l & 7) + ((l >> 3) & 1) * 8;
    const int acolb = ((l >> 4) & 1) * 16;

    auto load_chunk = [&](int c) {
        const int k0 = c * GK;
        const uint32_t db = sbase + (uint32_t)(c & 1) * BUF_B;
#pragma unroll
        for (int t = 0; t < 4; t++) {
            const __nv_bfloat16* src = tsrc[t];
            const int rb = (t < 2) ? bm : bn;
#pragma unroll
            for (int i = 0; i < 2; i++) {
                int u = tid + i * 256;
                int row = u >> 2, seg = u & 3;
                const void* gp = src + (size_t)(rb + row) * K + k0 + seg * 8;
                uint32_t sp = db + (uint32_t)(t * TILE_B + row * 80 + seg * 16);
                cp_async16(sp, gp);
            }
        }
        CP_COMMIT();
    };

    const int nchunk = K / GK;
    load_chunk(0);

    for (int c = 0; c < nchunk; c++) {
        CP_WAIT0();
        __syncthreads();
        if (c + 1 < nchunk) load_chunk(c + 1);

        const uint32_t bb = sbase + (uint32_t)(c & 1) * BUF_B;
#pragma unroll
        for (int kc = 0; kc < 2; kc++) {
            const uint32_t kcoff = (uint32_t)(kc * 32 + acolb);
            uint32_t ahi_[2][4];
            ldm4(ahi_[0], bb + (uint32_t)((mrow0 + arow) * 80) + kcoff);
            ldm4(ahi_[1], bb + (uint32_t)((mrow0 + 16 + arow) * 80) + kcoff);

            // pass 1: Ahi x Bhi   (B frags: (0,2) first n8, (1,3) second n8)
#pragma unroll
            for (int ni16 = 0; ni16 < 4; ni16++) {
                uint32_t bf[4];
                ldm4(bf, bb + 2 * TILE_B +
                             (uint32_t)((ncol0 + ni16 * 16 + arow) * 80) + kcoff);
                mma_bf16(acc[0][2 * ni16], ahi_[0], bf[0], bf[2]);
                mma_bf16(acc[1][2 * ni16], ahi_[1], bf[0], bf[2]);
                mma_bf16(acc[0][2 * ni16 + 1], ahi_[0], bf[1], bf[3]);
                mma_bf16(acc[1][2 * ni16 + 1], ahi_[1], bf[1], bf[3]);
            }
            // pass 2: Ahi x Blo
#pragma unroll
            for (int ni16 = 0; ni16 < 4; ni16++) {
                uint32_t bf[4];
                ldm4(bf, bb + 3 * TILE_B +
                             (uint32_t)((ncol0 + ni16 * 16 + arow) * 80) + kcoff);
                mma_bf16(acc[0][2 * ni16], ahi_[0], bf[0], bf[2]);
                mma_bf16(acc[1][2 * ni16], ahi_[1], bf[0], bf[2]);
                mma_bf16(acc[0][2 * ni16 + 1], ahi_[0], bf[1], bf[3]);
                mma_bf16(acc[1][2 * ni16 + 1], ahi_[1], bf[1], bf[3]);
            }
            // pass 3: Alo x Bhi
            uint32_t alo_[2][4];
            ldm4(alo_[0], bb + TILE_B + (uint32_t)((mrow0 + arow) * 80) + kcoff);
            ldm4(alo_[1],
                 bb + TILE_B + (uint32_t)((mrow0 + 16 + arow) * 80) + kcoff);
#pragma unroll
            for (int ni16 = 0; ni16 < 4; ni16++) {
                uint32_t bf[4];
                ldm4(bf, bb + 2 * TILE_B +
                             (uint32_t)((ncol0 + ni16 * 16 + arow) * 80) + kcoff);
                mma_bf16(acc[0][2 * ni16], alo_[0], bf[0], bf[2]);
                mma_bf16(acc[1][2 * ni16], alo_[1], bf[0], bf[2]);
                mma_bf16(acc[0][2 * ni16 + 1], alo_[0], bf[1], bf[3]);
                mma_bf16(acc[1][2 * ni16 + 1], alo_[1], bf[1], bf[3]);
            }
        }
    }

#pragma unroll
    for (int mi = 0; mi < 2; mi++) {
        const int r0 = bm + mrow0 + mi * 16 + g;
#pragma unroll
        for (int ni = 0; ni < 8; ni++) {
            const int col = bn + ncol0 + ni * 8 + 2 * t4;
            float b0v = 0.f, b1v = 0.f;
            if (HAS_BIAS) { b0v = bias[col]; b1v = bias[col + 1]; }
            float vals[4];
            vals[0] = acc[mi][ni][0] + b0v; vals[1] = acc[mi][ni][1] + b1v;
            vals[2] = acc[mi][ni][2] + b0v; vals[3] = acc[mi][ni][3] + b1v;
            if (ROUND_TF32) {
#pragma unroll
                for (int q = 0; q < 4; q++)
                    vals[q] = __uint_as_float(f2tf32(vals[q]));
            }
            float2 v0, v1;
            v0.x = vals[0]; v0.y = vals[1];
            v1.x = vals[2]; v1.y = vals[3];
            *(float2*)(C + (size_t)r0 * N + col) = v0;
            *(float2*)(C + (size_t)(r0 + 8) * N + col) = v1;
        }
    }
}

// ---------------------------------------------------------------------------
// Fused shuffled-Q flash attention (tf32 mma.sync).
// 256 threads (8 warps), 128 q-rows/block, KV tiles of 64, cp.async dbl-buffer.
// Epilogue writes bf16 hi/lo directly (feeds gemm2, no fp32 round-trip).
// ---------------------------------------------------------------------------
#define KSTR 68
#define VSTR 72
#define QSTR 70
#define KVBUF 8960                    // words: 64*68 + 64*72
#define VOFF 4352                     // words: 64*68
#define ATT_SMEM (2 * KVBUF * 4)      // 71680 bytes

__global__ void __launch_bounds__(256, 2) attn_kernel(
    const float* __restrict__ qkv, const int* __restrict__ perms,
    __nv_bfloat16* __restrict__ out_hi, __nv_bfloat16* __restrict__ out_lo) {
    extern __shared__ uint32_t sms[];
    const uint32_t sbase = smem_u32(sms);

    const int bh = blockIdx.y;
    const int b = bh / HEADS;
    const int h = bh % HEADS;
    const int q0 = blockIdx.x * 128;

    const int tid = threadIdx.x;
    const int w = tid >> 5, l = tid & 31;
    const int g = l >> 2, t4 = l & 3;
    const int qr0 = w * 16;

    const float* qkv_b = qkv + (size_t)b * SEQ * QKV_COLS;
    const int hoff = h * DHEAD;

    const int cp_row = tid >> 4;
    const int cp_seg = (tid & 15) * 4;

    auto issue_kv = [&](int t, int bsel) {
        const int kv0 = t * 64;
        const float* kb = qkv_b + (size_t)kv0 * QKV_COLS + hoff + INNER + cp_seg;
        const float* vb = kb + INNER;
        const uint32_t kd = sbase + (uint32_t)(bsel * KVBUF) * 4;
#pragma unroll
        for (int i = 0; i < 4; i++) {
            const int row = cp_row + i * 16;
            cp_async16(kd + (uint32_t)(row * KSTR + cp_seg) * 4,
                       kb + (size_t)row * QKV_COLS);
        }
#pragma unroll
        for (int i = 0; i < 4; i++) {
            const int row = cp_row + i * 16;
            cp_async16(kd + (uint32_t)(VOFF + row * VSTR + cp_seg) * 4,
                       vb + (size_t)row * QKV_COLS);
        }
        CP_COMMIT();
    };

    issue_kv(0, 0);

    const int* ph = perms + (size_t)h * (SEQ * DHEAD) + q0 * DHEAD;
#pragma unroll 4
    for (int it = 0; it < 32; it++) {
        int f = it * 256 + tid;
        int p = ph[f];
        int nn = p >> 6, dd = p & 63;
        int i = f >> 6, j = f & 63;
        sms[KVBUF + i * QSTR + j] =
            f2tf32(qkv_b[(size_t)nn * QKV_COLS + hoff + dd] * 0.125f);
    }
    __syncthreads();

    uint32_t qf[8][4];
#pragma unroll
    for (int kc = 0; kc < 8; kc++) {
        qf[kc][0] = sms[KVBUF + (qr0 + g) * QSTR + kc * 8 + t4];
        qf[kc][1] = sms[KVBUF + (qr0 + g + 8) * QSTR + kc * 8 + t4];
        qf[kc][2] = sms[KVBUF + (qr0 + g) * QSTR + kc * 8 + t4 + 4];
        qf[kc][3] = sms[KVBUF + (qr0 + g + 8) * QSTR + kc * 8 + t4 + 4];
    }
    __syncthreads();

    float m0 = -1e30f, m1 = -1e30f, l0 = 0.f, l1 = 0.f;
    float O[8][4];
#pragma unroll
    for (int dt = 0; dt < 8; dt++)
#pragma unroll
        for (int q = 0; q < 4; q++) O[dt][q] = 0.f;

    const int srcA = (l & 28) | (t4 >> 1);
    const int srcB = srcA | 2;
    const bool lo_lane = (t4 & 1) != 0;

    for (int t = 0; t < 16; t++) {
        if (t < 15) {
            issue_kv(t + 1, (t + 1) & 1);
            CP_WAIT1();
        } else {
            CP_WAIT0();
        }
        __syncthreads();

        const uint32_t kw = (uint32_t)(t & 1) * KVBUF;
        const uint32_t vw = kw + VOFF;

        float S[8][4];
#pragma unroll
        for (int nt = 0; nt < 8; nt++)
#pragma unroll
            for (int q = 0; q < 4; q++) S[nt][q] = 0.f;
#pragma unroll
        for (int kc = 0; kc < 8; kc++) {
#pragma unroll
            for (int nt = 0; nt < 8; nt++) {
                uint32_t b0 = sms[kw + (nt * 8 + g) * KSTR + kc * 8 + t4];
                uint32_t b1 = sms[kw + (nt * 8 + g) * KSTR + kc * 8 + t4 + 4];
                mma_tf32(S[nt], qf[kc], b0, b1);
            }
        }

        float mx0 = -1e30f, mx1 = -1e30f;
#pragma unroll
        for (int nt = 0; nt < 8; nt++) {
            mx0 = fmaxf(mx0, fmaxf(S[nt][0], S[nt][1]));
            mx1 = fmaxf(mx1, fmaxf(S[nt][2], S[nt][3]));
        }
        mx0 = fmaxf(mx0, __shfl_xor_sync(0xffffffffu, mx0, 1));
        mx0 = fmaxf(mx0, __shfl_xor_sync(0xffffffffu, mx0, 2));
        mx1 = fmaxf(mx1, __shfl_xor_sync(0xffffffffu, mx1, 1));
        mx1 = fmaxf(mx1, __shfl_xor_sync(0xffffffffu, mx1, 2));

        const float mn0 = fmaxf(m0, mx0);
        const float mn1 = fmaxf(m1, mx1);
        const float al0 = __expf(m0 - mn0);
        const float al1 = __expf(m1 - mn1);
        float sum0 = 0.f, sum1 = 0.f;
#pragma unroll
        for (int nt = 0; nt < 8; nt++) {
            S[nt][0] = __expf(S[nt][0] - mn0);
            S[nt][1] = __expf(S[nt][1] - mn0);
            S[nt][2] = __expf(S[nt][2] - mn1);
            S[nt][3] = __expf(S[nt][3] - mn1);
            sum0 += S[nt][0] + S[nt][1];
            sum1 += S[nt][2] + S[nt][3];
        }
        sum0 += __shfl_xor_sync(0xffffffffu, sum0, 1);
        sum0 += __shfl_xor_sync(0xffffffffu, sum0, 2);
        sum1 += __shfl_xor_sync(0xffffffffu, sum1, 1);
        sum1 += __shfl_xor_sync(0xffffffffu, sum1, 2);
        l0 = l0 * al0 + sum0;
        l1 = l1 * al1 + sum1;
        m0 = mn0; m1 = mn1;
#pragma unroll
        for (int dt = 0; dt < 8; dt++) {
            O[dt][0] *= al0; O[dt][1] *= al0;
            O[dt][2] *= al1; O[dt][3] *= al1;
        }

#pragma unroll
        for (int kc = 0; kc < 8; kc++) {
            uint32_t p0 = f2tf32(S[kc][0]);
            uint32_t p1 = f2tf32(S[kc][1]);
            uint32_t p2 = f2tf32(S[kc][2]);
            uint32_t p3 = f2tf32(S[kc][3]);
            uint32_t v00 = __shfl_sync(0xffffffffu, p0, srcA);
            uint32_t v01 = __shfl_sync(0xffffffffu, p1, srcA);
            uint32_t v10 = __shfl_sync(0xffffffffu, p2, srcA);
            uint32_t v11 = __shfl_sync(0xffffffffu, p3, srcA);
            uint32_t w00 = __shfl_sync(0xffffffffu, p0, srcB);
            uint32_t w01 = __shfl_sync(0xffffffffu, p1, srcB);
            uint32_t w10 = __shfl_sync(0xffffffffu, p2, srcB);
            uint32_t w11 = __shfl_sync(0xffffffffu, p3, srcB);
            uint32_t a[4];
            a[0] = lo_lane ? v01 : v00;
            a[1] = lo_lane ? v11 : v10;
            a[2] = lo_lane ? w01 : w00;
            a[3] = lo_lane ? w11 : w10;
#pragma unroll
            for (int dt = 0; dt < 8; dt++) {
                uint32_t b0 = sms[vw + (kc * 8 + t4) * VSTR + dt * 8 + g];
                uint32_t b1 = sms[vw + (kc * 8 + t4 + 4) * VSTR + dt * 8 + g];
                mma_tf32(O[dt], a, b0, b1);
            }
        }
        __syncthreads();
    }

    // Epilogue: normalize and write bf16 hi/lo pairs.
    const float inv0 = 1.0f / l0;
    const float inv1 = 1.0f / l1;
    const size_t r0off = ((size_t)b * SEQ + q0 + qr0 + g) * NDIM + hoff;
    const size_t r1off = r0off + (size_t)8 * NDIM;
#pragma unroll
    for (int dt = 0; dt < 8; dt++) {
        float f00 = O[dt][0] * inv0, f01 = O[dt][1] * inv0;
        float f10 = O[dt][2] * inv1, f11 = O[dt][3] * inv1;
        __nv_bfloat162 h0, h1, e0, e1;
        h0.x = __float2bfloat16(f00); h0.y = __float2bfloat16(f01);
        h1.x = __float2bfloat16(f10); h1.y = __float2bfloat16(f11);
        e0.x = __float2bfloat16(f00 - __bfloat162float(h0.x));
        e0.y = __float2bfloat16(f01 - __bfloat162float(h0.y));
        e1.x = __float2bfloat16(f10 - __bfloat162float(h1.x));
        e1.y = __float2bfloat16(f11 - __bfloat162float(h1.y));
        const int c = dt * 8 + 2 * t4;
        *(__nv_bfloat162*)(out_hi + r0off + c) = h0;
        *(__nv_bfloat162*)(out_lo + r0off + c) = e0;
        *(__nv_bfloat162*)(out_hi + r1off + c) = h1;
        *(__nv_bfloat162*)(out_lo + r1off + c) = e1;
    }
}

// ---------------------------------------------------------------------------
extern "C" void kernel_launch(void* const* d_in, const int* in_sizes, int n_in,
                              void* d_out, int out_size) {
    const float* x     = (const float*)d_in[0];
    const float* w_qkv = (const float*)d_in[1];
    const float* w_out = (const float*)d_in[2];
    const float* b_out = (const float*)d_in[3];
    const int*   perms = (const int*)d_in[4];
    float* out = (float*)d_out;

    float* qkv = nullptr;
    cudaGetSymbolAddress((void**)&qkv, g_qkv);
    __nv_bfloat16 *xhi, *xlo, *whi, *wlo, *ahi, *alo, *vhi, *vlo;
    cudaGetSymbolAddress((void**)&xhi, g_xhi);
    cudaGetSymbolAddress((void**)&xlo, g_xlo);
    cudaGetSymbolAddress((void**)&whi, g_whi);
    cudaGetSymbolAddress((void**)&wlo, g_wlo);
    cudaGetSymbolAddress((void**)&ahi, g_ahi);
    cudaGetSymbolAddress((void**)&alo, g_alo);
    cudaGetSymbolAddress((void**)&vhi, g_vhi);
    cudaGetSymbolAddress((void**)&vlo, g_vlo);

    cudaFuncSetAttribute(attn_kernel, cudaFuncAttributeMaxDynamicSharedMemorySize,
                         ATT_SMEM);
    cudaFuncSetAttribute((const void*)gemm_bf16x3<false, true>,
                         cudaFuncAttributeMaxDynamicSharedMemorySize, GEMM_SMEM);
    cudaFuncSetAttribute((const void*)gemm_bf16x3<true, false>,
                         cudaFuncAttributeMaxDynamicSharedMemorySize, GEMM_SMEM);

    // 1) split x / w_qkv / w_out into bf16 hi/lo
    {
        int n4 = ROWS_TOTAL * NDIM / 4;
        cvt_hilo<<<2048, 256>>>(x, xhi, xlo, n4);
        int m4 = QKV_COLS * NDIM / 4;
        cvt_hilo<<<1024, 256>>>(w_qkv, whi, wlo, m4);
        int v4 = NDIM * NDIM / 4;
        cvt_hilo<<<576, 256>>>(w_out, vhi, vlo, v4);
    }
    // 2) qkv = x @ w_qkv^T  (bf16x3 mma.sync, epilogue rounds to tf32)
    {
        dim3 grid(QKV_COLS / 128, ROWS_TOTAL / 128);  // (18, 64)
        gemm_bf16x3<false, true><<<grid, 256, GEMM_SMEM>>>(
            xhi, xlo, whi, wlo, nullptr, qkv, ROWS_TOTAL, QKV_COLS, NDIM);
    }
    // 3) fused shuffled-Q attention (tf32 mma.sync) -> bf16 hi/lo
    {
        dim3 grid(SEQ / 128, BATCH * HEADS);  // (8, 96)
        attn_kernel<<<grid, 256, ATT_SMEM>>>(qkv, perms, ahi, alo);
    }
    // 4) out = att @ w_out^T + b_out  (bf16x3 mma.sync)
    {
        dim3 grid(NDIM / 128, ROWS_TOTAL / 128);  // (6, 64)
        gemm_bf16x3<true, false><<<grid, 256, GEMM_SMEM>>>(
            ahi, alo, vhi, vlo, b_out, out, ROWS_TOTAL, NDIM, NDIM);
    }
}